// round 6
// baseline (speedup 1.0000x reference)
#include <cuda_runtime.h>
#include <cuda_bf16.h>
#include <cstdint>
#include <cstddef>

// Problem constants
#define BB 4
#define TT 2048
#define CC 1024
#define NH 16
#define HD 64
#define MM (BB * TT)          // 8192 rows
#define KK CC                 // 1024 inner dim (both GEMMs)
#define NQKV (3 * CC)         // 3072
#define NPROJ CC              // 1024

// ---------------- scratch (device globals; no allocations allowed) ----------
__device__ float g_qkv[(size_t)MM * NQKV];            // [B*T, 3C] fp32
__device__ float g_y  [(size_t)MM * CC];              // [B*T, C]  fp32
__device__ __nv_bfloat16 g_xh[(size_t)MM * KK];       // x hi/lo  [M,K]
__device__ __nv_bfloat16 g_xl[(size_t)MM * KK];
__device__ __nv_bfloat16 g_yh[(size_t)MM * KK];       // y hi/lo  [M,K]
__device__ __nv_bfloat16 g_yl[(size_t)MM * KK];
__device__ __nv_bfloat16 g_wah[(size_t)NQKV * KK];    // W_attn^T hi/lo [N,K]
__device__ __nv_bfloat16 g_wal[(size_t)NQKV * KK];
__device__ __nv_bfloat16 g_wph[(size_t)NPROJ * KK];   // W_proj^T hi/lo [N,K]
__device__ __nv_bfloat16 g_wpl[(size_t)NPROJ * KK];

// ---------------- PTX helpers (sm_80-portable only!) -------------------------
__device__ __forceinline__ uint32_t smem_to_u32(const void* p) {
    uint32_t a;
    asm("{ .reg .u64 t; cvta.to.shared.u64 t, %1; cvt.u32.u64 %0, t; }" : "=r"(a) : "l"(p));
    return a;
}
__device__ __forceinline__ void cpasync16(uint32_t sm, const void* g) {
    asm volatile("cp.async.ca.shared.global [%0], [%1], 16;" :: "r"(sm), "l"(g));
}
#define CP_COMMIT() asm volatile("cp.async.commit_group;" ::: "memory")
#define CP_WAIT0()  asm volatile("cp.async.wait_group 0;" ::: "memory")

__device__ __forceinline__ void ldmatrix_x4(uint32_t& r0, uint32_t& r1, uint32_t& r2,
                                            uint32_t& r3, uint32_t addr) {
    asm volatile("ldmatrix.sync.aligned.m8n8.x4.shared.b16 {%0,%1,%2,%3}, [%4];"
                 : "=r"(r0), "=r"(r1), "=r"(r2), "=r"(r3) : "r"(addr));
}
__device__ __forceinline__ void ldmatrix_x2(uint32_t& r0, uint32_t& r1, uint32_t addr) {
    asm volatile("ldmatrix.sync.aligned.m8n8.x2.shared.b16 {%0,%1}, [%2];"
                 : "=r"(r0), "=r"(r1) : "r"(addr));
}
__device__ __forceinline__ void mma_bf16(float* c, const uint32_t* a, const uint32_t* b) {
    asm volatile("mma.sync.aligned.m16n8k16.row.col.f32.bf16.bf16.f32 "
                 "{%0,%1,%2,%3}, {%4,%5,%6,%7}, {%8,%9}, {%0,%1,%2,%3};"
                 : "+f"(c[0]), "+f"(c[1]), "+f"(c[2]), "+f"(c[3])
                 : "r"(a[0]), "r"(a[1]), "r"(a[2]), "r"(a[3]), "r"(b[0]), "r"(b[1]));
}

// ---------------- prep kernels ----------------------------------------------
__global__ __launch_bounds__(256) void split_kernel(
    const float* __restrict__ src, __nv_bfloat16* __restrict__ hi,
    __nv_bfloat16* __restrict__ lo, int n4)
{
    int i = blockIdx.x * blockDim.x + threadIdx.x;
    if (i >= n4) return;
    float4 v = ((const float4*)src)[i];
    __nv_bfloat162 h0, h1, l0, l1;
    h0.x = __float2bfloat16(v.x); l0.x = __float2bfloat16(v.x - __bfloat162float(h0.x));
    h0.y = __float2bfloat16(v.y); l0.y = __float2bfloat16(v.y - __bfloat162float(h0.y));
    h1.x = __float2bfloat16(v.z); l1.x = __float2bfloat16(v.z - __bfloat162float(h1.x));
    h1.y = __float2bfloat16(v.w); l1.y = __float2bfloat16(v.w - __bfloat162float(h1.y));
    ((__nv_bfloat162*)hi)[i * 2 + 0] = h0;
    ((__nv_bfloat162*)hi)[i * 2 + 1] = h1;
    ((__nv_bfloat162*)lo)[i * 2 + 0] = l0;
    ((__nv_bfloat162*)lo)[i * 2 + 1] = l1;
}

__global__ __launch_bounds__(256) void transpose_split_kernel(
    const float* __restrict__ W, __nv_bfloat16* __restrict__ Th,
    __nv_bfloat16* __restrict__ Tl, int K, int N)
{
    __shared__ float tile[32][33];
    const int tx = threadIdx.x, ty = threadIdx.y;    // block (32,8)
    const int n0 = blockIdx.x * 32, k0 = blockIdx.y * 32;
    #pragma unroll
    for (int i = 0; i < 32; i += 8)
        tile[ty + i][tx] = W[(size_t)(k0 + ty + i) * N + n0 + tx];
    __syncthreads();
    #pragma unroll
    for (int i = 0; i < 32; i += 8) {
        float v = tile[tx][ty + i];
        __nv_bfloat16 h = __float2bfloat16(v);
        __nv_bfloat16 l = __float2bfloat16(v - __bfloat162float(h));
        size_t o = (size_t)(n0 + ty + i) * K + k0 + tx;
        Th[o] = h; Tl[o] = l;
    }
}

// ---------------- split-bf16 mma.sync GEMM -----------------------------------
// D[m,n] = sum_k A[m,k]*B[n,k] (+bias[n]); A,B pre-split bf16 hi/lo, row-major,
// leading dim K. CTA tile 128x128, BK=32, 8 warps (2Mx4N), warp tile 64x32.
// SMEM: 4 tiles (Ah,Al,Bh,Bl) of [128][40] bf16 (80B stride), double buffered.
#define GST      40                        // smem row stride in bf16 elems
#define GTILE_B  (128 * GST * 2)           // 10240 bytes per tile
#define GSTAGE_B (4 * GTILE_B)             // 40960 bytes per stage
#define GSMEM_TOTAL (2 * GSTAGE_B)         // 81920

__global__ __launch_bounds__(256) void mma_gemm_kernel(
    const __nv_bfloat16* __restrict__ Ah, const __nv_bfloat16* __restrict__ Al,
    const __nv_bfloat16* __restrict__ Bh, const __nv_bfloat16* __restrict__ Bl,
    const float* __restrict__ bias, float* __restrict__ C, int N, int K)
{
    extern __shared__ char smem[];
    const uint32_t sbase = smem_to_u32(smem);
    const int tid = threadIdx.x;
    const int wid = tid >> 5, lane = tid & 31;
    const int m0 = blockIdx.y * 128;
    const int n0 = blockIdx.x * 128;
    const int warp_m = wid >> 2;           // 0..1 -> 64 rows each
    const int warp_n = wid & 3;            // 0..3 -> 32 cols each

    const __nv_bfloat16* gA[2] = { Ah + (size_t)m0 * K, Al + (size_t)m0 * K };
    const __nv_bfloat16* gB[2] = { Bh + (size_t)n0 * K, Bl + (size_t)n0 * K };

    // g2s mapping: per tile 512 x 16B chunks; thread does chunks tid, tid+256
    const int r0c = tid >> 2, c0c = tid & 3;   // chunk tid
    // (chunk tid+256: row r0c+64, same c0c)

    auto issue_stage = [&](int stage, int kof) {
        uint32_t sb = sbase + stage * GSTAGE_B;
        #pragma unroll
        for (int t = 0; t < 4; t++) {
            const __nv_bfloat16* g = (t < 2) ? gA[t] : gB[t - 2];
            uint32_t st = sb + t * GTILE_B;
            cpasync16(st + (uint32_t)(r0c * (GST * 2) + c0c * 16),
                      (const char*)g + (size_t)r0c * K * 2 + kof * 2 + c0c * 16);
            cpasync16(st + (uint32_t)((r0c + 64) * (GST * 2) + c0c * 16),
                      (const char*)g + (size_t)(r0c + 64) * K * 2 + kof * 2 + c0c * 16);
        }
    };

    float acc[4][4][4];
    #pragma unroll
    for (int i = 0; i < 4; i++)
        #pragma unroll
        for (int j = 0; j < 4; j++)
            #pragma unroll
            for (int r = 0; r < 4; r++) acc[i][j][r] = 0.f;

    const int NC = K >> 5;                 // 32 K-chunks
    issue_stage(0, 0);
    CP_COMMIT();

    // ldmatrix address components (within a tile)
    const int a_row = (lane & 15);               // + mt*16 + warp_m*64
    const int a_col = (lane >> 4) * 8;           // + ks*16
    const int b_row = (lane & 7);                // + nt*8 + warp_n*32
    const int b_col = ((lane >> 3) & 1) * 8;     // + ks*16

    for (int kc = 0; kc < NC; kc++) {
        CP_WAIT0();
        __syncthreads();
        const int cur = kc & 1;
        if (kc + 1 < NC) { issue_stage(cur ^ 1, (kc + 1) << 5); CP_COMMIT(); }

        const uint32_t sb = sbase + cur * GSTAGE_B;
        const uint32_t sAh = sb;
        const uint32_t sAl = sb + GTILE_B;
        const uint32_t sBh = sb + 2 * GTILE_B;
        const uint32_t sBl = sb + 3 * GTILE_B;

        #pragma unroll
        for (int ks = 0; ks < 2; ks++) {
            const int kcol = ks * 16;
            uint32_t ah[4][4], al[4][4], bh[4][2], bl[4][2];
            #pragma unroll
            for (int mt = 0; mt < 4; mt++) {
                const uint32_t off = (uint32_t)((warp_m * 64 + mt * 16 + a_row) * (GST * 2)
                                                + (kcol + a_col) * 2);
                ldmatrix_x4(ah[mt][0], ah[mt][1], ah[mt][2], ah[mt][3], sAh + off);
                ldmatrix_x4(al[mt][0], al[mt][1], al[mt][2], al[mt][3], sAl + off);
            }
            #pragma unroll
            for (int nt = 0; nt < 4; nt++) {
                const uint32_t off = (uint32_t)((warp_n * 32 + nt * 8 + b_row) * (GST * 2)
                                                + (kcol + b_col) * 2);
                ldmatrix_x2(bh[nt][0], bh[nt][1], sBh + off);
                ldmatrix_x2(bl[nt][0], bl[nt][1], sBl + off);
            }
            #pragma unroll
            for (int mt = 0; mt < 4; mt++)
                #pragma unroll
                for (int nt = 0; nt < 4; nt++) {
                    mma_bf16(acc[mt][nt], ah[mt], bh[nt]);
                    mma_bf16(acc[mt][nt], ah[mt], bl[nt]);
                    mma_bf16(acc[mt][nt], al[mt], bh[nt]);
                }
        }
        __syncthreads();
    }

    // epilogue: acc[mt][nt] regs c0..c3 -> rows m,(m+8), cols n,(n+1)
    const int er = lane >> 2, ec = (lane & 3) * 2;
    #pragma unroll
    for (int mt = 0; mt < 4; mt++) {
        const int mrow = m0 + warp_m * 64 + mt * 16 + er;
        #pragma unroll
        for (int nt = 0; nt < 4; nt++) {
            const int ncol = n0 + warp_n * 32 + nt * 8 + ec;
            float2 v0 = { acc[mt][nt][0] + bias[ncol], acc[mt][nt][1] + bias[ncol + 1] };
            float2 v1 = { acc[mt][nt][2] + bias[ncol], acc[mt][nt][3] + bias[ncol + 1] };
            *(float2*)(C + (size_t)mrow * N + ncol) = v0;
            *(float2*)(C + (size_t)(mrow + 8) * N + ncol) = v1;
        }
    }
}

// ---------------- causal flash attention (unchanged) -------------------------
#define AT_QROWS 128
#define AT_KTILE 64

__global__ __launch_bounds__(128) void attn_kernel()
{
    const int qt  = blockIdx.x;
    const int h   = blockIdx.y;
    const int b   = blockIdx.z;
    const int tid = threadIdx.x;
    const int qg  = qt * AT_QROWS + tid;

    __shared__ float4 kx[AT_KTILE][HD / 4];
    __shared__ float4 vx[AT_KTILE][HD / 4];

    const float* qptr = g_qkv + ((size_t)(b * TT + qg)) * 3 * CC + h * HD;
    float4 q[HD / 4];
    #pragma unroll
    for (int i = 0; i < HD / 4; i++) q[i] = ((const float4*)qptr)[i];

    float o[HD];
    #pragma unroll
    for (int d = 0; d < HD; d++) o[d] = 0.f;
    float m = -1e30f, l = 0.f;
    const float scale = 0.125f;

    const int ktiles = 2 * qt + 2;
    for (int kt = 0; kt < ktiles; kt++) {
        const int k0 = kt * AT_KTILE;
        __syncthreads();
        const float* kbase = g_qkv + ((size_t)(b * TT + k0)) * 3 * CC + CC + h * HD;
        const float* vbase = kbase + CC;
        #pragma unroll
        for (int i = 0; i < 8; i++) {
            const int lin = tid + i * 128;
            const int r   = lin >> 4;
            const int c4  = lin & 15;
            kx[r][c4] = *(const float4*)(kbase + (size_t)r * 3 * CC + c4 * 4);
            vx[r][c4] = *(const float4*)(vbase + (size_t)r * 3 * CC + c4 * 4);
        }
        __syncthreads();

        #pragma unroll 1
        for (int ch = 0; ch < 4; ch++) {
            float s[16];
            #pragma unroll
            for (int j = 0; j < 16; j++) {
                const int kr = ch * 16 + j;
                float ax = 0.f, ay = 0.f, az = 0.f, aw = 0.f;
                #pragma unroll
                for (int d4 = 0; d4 < HD / 4; d4++) {
                    float4 kv = kx[kr][d4];
                    ax += q[d4].x * kv.x;
                    ay += q[d4].y * kv.y;
                    az += q[d4].z * kv.z;
                    aw += q[d4].w * kv.w;
                }
                float sv = ((ax + ay) + (az + aw)) * scale;
                if (k0 + kr > qg) sv = -1e30f;
                s[j] = sv;
            }
            float mc = s[0];
            #pragma unroll
            for (int j = 1; j < 16; j++) mc = fmaxf(mc, s[j]);
            const float mn   = fmaxf(m, mc);
            const float corr = __expf(m - mn);
            float ps = 0.f;
            #pragma unroll
            for (int j = 0; j < 16; j++) { s[j] = __expf(s[j] - mn); ps += s[j]; }
            l = l * corr + ps;
            m = mn;
            #pragma unroll
            for (int d = 0; d < HD; d++) o[d] *= corr;
            #pragma unroll
            for (int j = 0; j < 16; j++) {
                const int kr = ch * 16 + j;
                const float pj = s[j];
                #pragma unroll
                for (int d4 = 0; d4 < HD / 4; d4++) {
                    float4 vv = vx[kr][d4];
                    o[d4 * 4 + 0] += pj * vv.x;
                    o[d4 * 4 + 1] += pj * vv.y;
                    o[d4 * 4 + 2] += pj * vv.z;
                    o[d4 * 4 + 3] += pj * vv.w;
                }
            }
        }
    }

    const float inv = 1.f / l;
    float* yo = g_y + ((size_t)(b * TT + qg)) * CC + h * HD;
    #pragma unroll
    for (int d4 = 0; d4 < HD / 4; d4++) {
        float4 ov;
        ov.x = o[d4 * 4 + 0] * inv;
        ov.y = o[d4 * 4 + 1] * inv;
        ov.z = o[d4 * 4 + 2] * inv;
        ov.w = o[d4 * 4 + 3] * inv;
        ((float4*)yo)[d4] = ov;
    }
}

// ---------------- launch -----------------------------------------------------
extern "C" void kernel_launch(void* const* d_in, const int* in_sizes, int n_in,
                              void* d_out, int out_size)
{
    (void)in_sizes; (void)n_in; (void)out_size;
    const float* x  = (const float*)d_in[0];
    const float* Wa = (const float*)d_in[1];
    const float* ba = (const float*)d_in[2];
    const float* Wp = (const float*)d_in[3];
    const float* bp = (const float*)d_in[4];
    float* out = (float*)d_out;

    cudaFuncSetAttribute(mma_gemm_kernel, cudaFuncAttributeMaxDynamicSharedMemorySize, GSMEM_TOTAL);

    __nv_bfloat16 *xh, *xl, *yh, *yl, *wah, *wal, *wph, *wpl;
    cudaGetSymbolAddress((void**)&xh,  g_xh);  cudaGetSymbolAddress((void**)&xl,  g_xl);
    cudaGetSymbolAddress((void**)&yh,  g_yh);  cudaGetSymbolAddress((void**)&yl,  g_yl);
    cudaGetSymbolAddress((void**)&wah, g_wah); cudaGetSymbolAddress((void**)&wal, g_wal);
    cudaGetSymbolAddress((void**)&wph, g_wph); cudaGetSymbolAddress((void**)&wpl, g_wpl);
    float *qkv, *y;
    cudaGetSymbolAddress((void**)&qkv, g_qkv); cudaGetSymbolAddress((void**)&y, g_y);

    // 1) split x -> bf16 hi/lo
    {
        int n4 = MM * KK / 4;
        split_kernel<<<(n4 + 255) / 256, 256>>>(x, xh, xl, n4);
    }
    // 2) transpose+split weights
    {
        dim3 blk(32, 8);
        transpose_split_kernel<<<dim3(NQKV / 32, KK / 32), blk>>>(Wa, wah, wal, KK, NQKV);
        transpose_split_kernel<<<dim3(NPROJ / 32, KK / 32), blk>>>(Wp, wph, wpl, KK, NPROJ);
    }
    // 3) QKV GEMM (mma.sync): [8192,1024]@[1024,3072]+b -> g_qkv
    mma_gemm_kernel<<<dim3(NQKV / 128, MM / 128), 256, GSMEM_TOTAL>>>(
        xh, xl, wah, wal, ba, qkv, NQKV, KK);
    // 4) causal flash attention: g_qkv -> g_y
    attn_kernel<<<dim3(TT / AT_QROWS, NH, BB), 128>>>();
    // 5) split y -> bf16 hi/lo
    {
        int n4 = MM * KK / 4;
        split_kernel<<<(n4 + 255) / 256, 256>>>(y, yh, yl, n4);
    }
    // 6) proj GEMM (mma.sync): [8192,1024]@[1024,1024]+b -> out
    mma_gemm_kernel<<<dim3(NPROJ / 128, MM / 128), 256, GSMEM_TOTAL>>>(
        yh, yl, wph, wpl, bp, out, NPROJ, KK);
}

// round 7
// speedup vs baseline: 2.2873x; 2.2873x over previous
#include <cuda_runtime.h>
#include <cuda_bf16.h>
#include <cstdint>
#include <cstddef>

// Problem constants
#define BB 4
#define TT 2048
#define CC 1024
#define NH 16
#define HD 64
#define MM (BB * TT)          // 8192 rows
#define KK CC                 // 1024 inner dim (both GEMMs)
#define NQKV (3 * CC)         // 3072
#define NPROJ CC              // 1024

// ---------------- scratch (device globals; no allocations allowed) ----------
// Q,K,V split bf16 in [B,H,T,64] layout (written by QKV GEMM epilogue)
__device__ __nv_bfloat16 g_qh[(size_t)MM * CC];
__device__ __nv_bfloat16 g_ql[(size_t)MM * CC];
__device__ __nv_bfloat16 g_kh[(size_t)MM * CC];
__device__ __nv_bfloat16 g_kl[(size_t)MM * CC];
__device__ __nv_bfloat16 g_vh[(size_t)MM * CC];
__device__ __nv_bfloat16 g_vl[(size_t)MM * CC];
// attention output split bf16, [M][C] row-major (proj GEMM A input)
__device__ __nv_bfloat16 g_yh[(size_t)MM * KK];
__device__ __nv_bfloat16 g_yl[(size_t)MM * KK];
// x split, weight transpose+split
__device__ __nv_bfloat16 g_xh[(size_t)MM * KK];
__device__ __nv_bfloat16 g_xl[(size_t)MM * KK];
__device__ __nv_bfloat16 g_wah[(size_t)NQKV * KK];
__device__ __nv_bfloat16 g_wal[(size_t)NQKV * KK];
__device__ __nv_bfloat16 g_wph[(size_t)NPROJ * KK];
__device__ __nv_bfloat16 g_wpl[(size_t)NPROJ * KK];

// ---------------- PTX helpers (sm_80-portable only) --------------------------
__device__ __forceinline__ uint32_t smem_to_u32(const void* p) {
    uint32_t a;
    asm("{ .reg .u64 t; cvta.to.shared.u64 t, %1; cvt.u32.u64 %0, t; }" : "=r"(a) : "l"(p));
    return a;
}
__device__ __forceinline__ void cpasync16(uint32_t sm, const void* g) {
    asm volatile("cp.async.ca.shared.global [%0], [%1], 16;" :: "r"(sm), "l"(g));
}
#define CP_COMMIT() asm volatile("cp.async.commit_group;" ::: "memory")
#define CP_WAIT0()  asm volatile("cp.async.wait_group 0;" ::: "memory")

__device__ __forceinline__ void ldmatrix_x4(uint32_t& r0, uint32_t& r1, uint32_t& r2,
                                            uint32_t& r3, uint32_t addr) {
    asm volatile("ldmatrix.sync.aligned.m8n8.x4.shared.b16 {%0,%1,%2,%3}, [%4];"
                 : "=r"(r0), "=r"(r1), "=r"(r2), "=r"(r3) : "r"(addr));
}
__device__ __forceinline__ void ldmatrix_x4_trans(uint32_t& r0, uint32_t& r1, uint32_t& r2,
                                                  uint32_t& r3, uint32_t addr) {
    asm volatile("ldmatrix.sync.aligned.m8n8.x4.trans.shared.b16 {%0,%1,%2,%3}, [%4];"
                 : "=r"(r0), "=r"(r1), "=r"(r2), "=r"(r3) : "r"(addr));
}
__device__ __forceinline__ void ldmatrix_x2(uint32_t& r0, uint32_t& r1, uint32_t addr) {
    asm volatile("ldmatrix.sync.aligned.m8n8.x2.shared.b16 {%0,%1}, [%2];"
                 : "=r"(r0), "=r"(r1) : "r"(addr));
}
__device__ __forceinline__ void mma_bf16(float* c, const uint32_t* a, const uint32_t* b) {
    asm volatile("mma.sync.aligned.m16n8k16.row.col.f32.bf16.bf16.f32 "
                 "{%0,%1,%2,%3}, {%4,%5,%6,%7}, {%8,%9}, {%0,%1,%2,%3};"
                 : "+f"(c[0]), "+f"(c[1]), "+f"(c[2]), "+f"(c[3])
                 : "r"(a[0]), "r"(a[1]), "r"(a[2]), "r"(a[3]), "r"(b[0]), "r"(b[1]));
}
__device__ __forceinline__ uint32_t pack_bf16(__nv_bfloat16 a, __nv_bfloat16 b) {
    __nv_bfloat162 t; t.x = a; t.y = b;
    return *(uint32_t*)&t;
}

// ---------------- prep kernels ----------------------------------------------
__global__ __launch_bounds__(256) void split_kernel(
    const float* __restrict__ src, __nv_bfloat16* __restrict__ hi,
    __nv_bfloat16* __restrict__ lo, int n4)
{
    int i = blockIdx.x * blockDim.x + threadIdx.x;
    if (i >= n4) return;
    float4 v = ((const float4*)src)[i];
    __nv_bfloat162 h0, h1, l0, l1;
    h0.x = __float2bfloat16(v.x); l0.x = __float2bfloat16(v.x - __bfloat162float(h0.x));
    h0.y = __float2bfloat16(v.y); l0.y = __float2bfloat16(v.y - __bfloat162float(h0.y));
    h1.x = __float2bfloat16(v.z); l1.x = __float2bfloat16(v.z - __bfloat162float(h1.x));
    h1.y = __float2bfloat16(v.w); l1.y = __float2bfloat16(v.w - __bfloat162float(h1.y));
    ((__nv_bfloat162*)hi)[i * 2 + 0] = h0;
    ((__nv_bfloat162*)hi)[i * 2 + 1] = h1;
    ((__nv_bfloat162*)lo)[i * 2 + 0] = l0;
    ((__nv_bfloat162*)lo)[i * 2 + 1] = l1;
}

__global__ __launch_bounds__(256) void transpose_split_kernel(
    const float* __restrict__ W, __nv_bfloat16* __restrict__ Th,
    __nv_bfloat16* __restrict__ Tl, int K, int N)
{
    __shared__ float tile[32][33];
    const int tx = threadIdx.x, ty = threadIdx.y;    // block (32,8)
    const int n0 = blockIdx.x * 32, k0 = blockIdx.y * 32;
    #pragma unroll
    for (int i = 0; i < 32; i += 8)
        tile[ty + i][tx] = W[(size_t)(k0 + ty + i) * N + n0 + tx];
    __syncthreads();
    #pragma unroll
    for (int i = 0; i < 32; i += 8) {
        float v = tile[tx][ty + i];
        __nv_bfloat16 h = __float2bfloat16(v);
        __nv_bfloat16 l = __float2bfloat16(v - __bfloat162float(h));
        size_t o = (size_t)(n0 + ty + i) * K + k0 + tx;
        Th[o] = h; Tl[o] = l;
    }
}

// ---------------- split-bf16 mma.sync GEMM -----------------------------------
// MODE 0: C fp32 = A@B^T + bias     MODE 1: QKV epilogue -> split [B,H,T,64]
#define GST      40                        // smem row stride in bf16 elems
#define GTILE_B  (128 * GST * 2)           // 10240 bytes per tile
#define GSTAGE_B (4 * GTILE_B)             // 40960 bytes per stage
#define GSMEM_TOTAL (2 * GSTAGE_B)         // 81920

template <int MODE>
__global__ __launch_bounds__(256, 2) void mma_gemm_kernel(
    const __nv_bfloat16* __restrict__ Ah, const __nv_bfloat16* __restrict__ Al,
    const __nv_bfloat16* __restrict__ Bh, const __nv_bfloat16* __restrict__ Bl,
    const float* __restrict__ bias, float* __restrict__ C, int N, int K)
{
    extern __shared__ char smem[];
    const uint32_t sbase = smem_to_u32(smem);
    const int tid = threadIdx.x;
    const int wid = tid >> 5, lane = tid & 31;
    const int m0 = blockIdx.y * 128;
    const int n0 = blockIdx.x * 128;
    const int warp_m = wid >> 2;
    const int warp_n = wid & 3;

    const __nv_bfloat16* gA[2] = { Ah + (size_t)m0 * K, Al + (size_t)m0 * K };
    const __nv_bfloat16* gB[2] = { Bh + (size_t)n0 * K, Bl + (size_t)n0 * K };

    const int r0c = tid >> 2, c0c = tid & 3;

    auto issue_stage = [&](int stage, int kof) {
        uint32_t sb = sbase + stage * GSTAGE_B;
        #pragma unroll
        for (int t = 0; t < 4; t++) {
            const __nv_bfloat16* g = (t < 2) ? gA[t] : gB[t - 2];
            uint32_t st = sb + t * GTILE_B;
            cpasync16(st + (uint32_t)(r0c * (GST * 2) + c0c * 16),
                      (const char*)g + (size_t)r0c * K * 2 + kof * 2 + c0c * 16);
            cpasync16(st + (uint32_t)((r0c + 64) * (GST * 2) + c0c * 16),
                      (const char*)g + (size_t)(r0c + 64) * K * 2 + kof * 2 + c0c * 16);
        }
    };

    float acc[4][4][4];
    #pragma unroll
    for (int i = 0; i < 4; i++)
        #pragma unroll
        for (int j = 0; j < 4; j++)
            #pragma unroll
            for (int r = 0; r < 4; r++) acc[i][j][r] = 0.f;

    const int NC = K >> 5;
    issue_stage(0, 0);
    CP_COMMIT();

    const int a_row = (lane & 15);
    const int a_col = (lane >> 4) * 8;
    const int b_row = (lane & 7);
    const int b_col = ((lane >> 3) & 1) * 8;

    for (int kc = 0; kc < NC; kc++) {
        CP_WAIT0();
        __syncthreads();
        const int cur = kc & 1;
        if (kc + 1 < NC) { issue_stage(cur ^ 1, (kc + 1) << 5); CP_COMMIT(); }

        const uint32_t sb = sbase + cur * GSTAGE_B;
        const uint32_t sAh = sb;
        const uint32_t sAl = sb + GTILE_B;
        const uint32_t sBh = sb + 2 * GTILE_B;
        const uint32_t sBl = sb + 3 * GTILE_B;

        #pragma unroll
        for (int ks = 0; ks < 2; ks++) {
            const int kcol = ks * 16;
            uint32_t ah[4][4], al[4][4], bh[4][2], bl[4][2];
            #pragma unroll
            for (int mt = 0; mt < 4; mt++) {
                const uint32_t off = (uint32_t)((warp_m * 64 + mt * 16 + a_row) * (GST * 2)
                                                + (kcol + a_col) * 2);
                ldmatrix_x4(ah[mt][0], ah[mt][1], ah[mt][2], ah[mt][3], sAh + off);
                ldmatrix_x4(al[mt][0], al[mt][1], al[mt][2], al[mt][3], sAl + off);
            }
            #pragma unroll
            for (int nt = 0; nt < 4; nt++) {
                const uint32_t off = (uint32_t)((warp_n * 32 + nt * 8 + b_row) * (GST * 2)
                                                + (kcol + b_col) * 2);
                ldmatrix_x2(bh[nt][0], bh[nt][1], sBh + off);
                ldmatrix_x2(bl[nt][0], bl[nt][1], sBl + off);
            }
            #pragma unroll
            for (int mt = 0; mt < 4; mt++)
                #pragma unroll
                for (int nt = 0; nt < 4; nt++) {
                    mma_bf16(acc[mt][nt], ah[mt], bh[nt]);
                    mma_bf16(acc[mt][nt], ah[mt], bl[nt]);
                    mma_bf16(acc[mt][nt], al[mt], bh[nt]);
                }
        }
        __syncthreads();
    }

    const int er = lane >> 2, ec = (lane & 3) * 2;
    if (MODE == 0) {
        #pragma unroll
        for (int mt = 0; mt < 4; mt++) {
            const int mrow = m0 + warp_m * 64 + mt * 16 + er;
            #pragma unroll
            for (int nt = 0; nt < 4; nt++) {
                const int ncol = n0 + warp_n * 32 + nt * 8 + ec;
                float2 v0 = { acc[mt][nt][0] + bias[ncol], acc[mt][nt][1] + bias[ncol + 1] };
                float2 v1 = { acc[mt][nt][2] + bias[ncol], acc[mt][nt][3] + bias[ncol + 1] };
                *(float2*)(C + (size_t)mrow * N + ncol) = v0;
                *(float2*)(C + (size_t)(mrow + 8) * N + ncol) = v1;
            }
        }
    } else {
        // QKV epilogue: comp constant per CTA (n0 multiple of 128)
        const int comp = n0 >> 10;
        __nv_bfloat16* dh = (comp == 0) ? g_qh : (comp == 1) ? g_kh : g_vh;
        __nv_bfloat16* dl = (comp == 0) ? g_ql : (comp == 1) ? g_kl : g_vl;
        const float sc = (comp == 0) ? 0.125f : 1.0f;   // fold 1/sqrt(hd) into Q
        #pragma unroll
        for (int mt = 0; mt < 4; mt++) {
            #pragma unroll
            for (int nt = 0; nt < 4; nt++) {
                const int ncol = n0 + warp_n * 32 + nt * 8 + ec;
                const int hh = (ncol & 1023) >> 6;
                const int dd = ncol & 63;
                #pragma unroll
                for (int rr = 0; rr < 2; rr++) {
                    const int mrow = m0 + warp_m * 64 + mt * 16 + er + rr * 8;
                    const int bb = mrow >> 11, t = mrow & 2047;
                    const size_t idx = (((size_t)(bb * NH + hh)) * TT + t) * HD + dd;
                    float v0 = (acc[mt][nt][rr * 2 + 0] + bias[ncol]) * sc;
                    float v1 = (acc[mt][nt][rr * 2 + 1] + bias[ncol + 1]) * sc;
                    __nv_bfloat16 h0 = __float2bfloat16(v0);
                    __nv_bfloat16 h1 = __float2bfloat16(v1);
                    __nv_bfloat16 l0 = __float2bfloat16(v0 - __bfloat162float(h0));
                    __nv_bfloat16 l1 = __float2bfloat16(v1 - __bfloat162float(h1));
                    *(uint32_t*)(dh + idx) = pack_bf16(h0, h1);
                    *(uint32_t*)(dl + idx) = pack_bf16(l0, l1);
                }
            }
        }
    }
}

// ---------------- tensor-core causal flash attention -------------------------
// CTA: 64 query rows, 4 warps (16 rows each). Key tiles of 64, double-buffered.
// S = QhKh+QhKl+QlKh (fp32-accurate); softmax fp32 on fragments;
// PV = PhVh+PhVl+PlVh with V fragments via ldmatrix.trans.
#define AST      72                         // smem row stride elems (144B)
#define ATILE_B  (64 * AST * 2)             // 9216 bytes
#define ASTAGE_B (4 * ATILE_B)              // 36864 (Kh,Kl,Vh,Vl)
#define ASMEM    (2 * ASTAGE_B)             // 73728

__global__ __launch_bounds__(128) void attn_mma_kernel()
{
    extern __shared__ char smem[];
    const uint32_t sbase = smem_to_u32(smem);
    const int tid = threadIdx.x;
    const int warp = tid >> 5, lane = tid & 31;
    const int qt = blockIdx.x, h = blockIdx.y, b = blockIdx.z;

    const size_t plane = ((size_t)(b * NH + h)) * TT * HD;
    const __nv_bfloat16* Qh = g_qh + plane;
    const __nv_bfloat16* Ql = g_ql + plane;
    const __nv_bfloat16* Kh = g_kh + plane;
    const __nv_bfloat16* Kl = g_kl + plane;
    const __nv_bfloat16* Vh = g_vh + plane;
    const __nv_bfloat16* Vl = g_vl + plane;

    // ---- load Q tile (rows qt*64..+63) into stage0 tiles 0,1 ----
    {
        const __nv_bfloat16* src[2] = { Qh + (size_t)qt * 64 * HD, Ql + (size_t)qt * 64 * HD };
        #pragma unroll
        for (int t = 0; t < 2; t++)
            #pragma unroll
            for (int i = 0; i < 4; i++) {
                int c = tid + i * 128;
                int row = c >> 3, cc = c & 7;
                cpasync16(sbase + t * ATILE_B + (uint32_t)(row * (AST * 2) + cc * 16),
                          (const char*)src[t] + (size_t)row * 128 + cc * 16);
            }
    }
    CP_COMMIT();
    CP_WAIT0();
    __syncthreads();

    // ---- Q fragments to registers ----
    uint32_t qfh[4][4], qfl[4][4];
    {
        const int a_row = lane & 15;
        const int a_col = (lane >> 4) * 8;
        #pragma unroll
        for (int ks = 0; ks < 4; ks++) {
            const uint32_t off = (uint32_t)((warp * 16 + a_row) * (AST * 2)
                                            + (ks * 16 + a_col) * 2);
            ldmatrix_x4(qfh[ks][0], qfh[ks][1], qfh[ks][2], qfh[ks][3], sbase + off);
            ldmatrix_x4(qfl[ks][0], qfl[ks][1], qfl[ks][2], qfl[ks][3],
                        sbase + ATILE_B + off);
        }
    }
    __syncthreads();   // all warps done reading Q smem before kt=0 overwrites it

    auto issue_kv = [&](int stage, int kt) {
        const __nv_bfloat16* src[4] = {
            Kh + (size_t)kt * 64 * HD, Kl + (size_t)kt * 64 * HD,
            Vh + (size_t)kt * 64 * HD, Vl + (size_t)kt * 64 * HD };
        uint32_t sb = sbase + stage * ASTAGE_B;
        #pragma unroll
        for (int t = 0; t < 4; t++)
            #pragma unroll
            for (int i = 0; i < 4; i++) {
                int c = tid + i * 128;
                int row = c >> 3, cc = c & 7;
                cpasync16(sb + t * ATILE_B + (uint32_t)(row * (AST * 2) + cc * 16),
                          (const char*)src[t] + (size_t)row * 128 + cc * 16);
            }
    };

    issue_kv(0, 0);
    CP_COMMIT();

    float O[8][4];
    #pragma unroll
    for (int i = 0; i < 8; i++)
        #pragma unroll
        for (int j = 0; j < 4; j++) O[i][j] = 0.f;
    float mrun0 = -1e30f, mrun1 = -1e30f, lrun0 = 0.f, lrun1 = 0.f;

    const int qrow_lo0 = warp * 16 + (lane >> 2);      // local query row (c0/c1)
    const int qrow_lo1 = qrow_lo0 + 8;                 // (c2/c3)

    for (int kt = 0; kt <= qt; kt++) {
        CP_WAIT0();
        __syncthreads();
        const int cur = kt & 1;
        if (kt < qt) { issue_kv(cur ^ 1, kt + 1); CP_COMMIT(); }

        const uint32_t sKh = sbase + cur * ASTAGE_B;
        const uint32_t sKl = sKh + ATILE_B;
        const uint32_t sVh = sKh + 2 * ATILE_B;
        const uint32_t sVl = sKh + 3 * ATILE_B;

        // ---- S = Q @ K^T (3-way split) ----
        float sS[8][4];
        #pragma unroll
        for (int i = 0; i < 8; i++)
            #pragma unroll
            for (int j = 0; j < 4; j++) sS[i][j] = 0.f;

        {
            const int krow = ((lane >> 3) & 1) * 8 + (lane & 7);
            const int kcol = (lane >> 4) * 8;
            #pragma unroll
            for (int ntp = 0; ntp < 4; ntp++) {
                uint32_t kbh[4][4], kbl[4][4];
                #pragma unroll
                for (int ks = 0; ks < 4; ks++) {
                    const uint32_t off = (uint32_t)((ntp * 16 + krow) * (AST * 2)
                                                    + (ks * 16 + kcol) * 2);
                    ldmatrix_x4(kbh[ks][0], kbh[ks][1], kbh[ks][2], kbh[ks][3], sKh + off);
                    ldmatrix_x4(kbl[ks][0], kbl[ks][1], kbl[ks][2], kbl[ks][3], sKl + off);
                }
                #pragma unroll
                for (int ks = 0; ks < 4; ks++) {
                    uint32_t b0h[2] = { kbh[ks][0], kbh[ks][2] };
                    uint32_t b1h[2] = { kbh[ks][1], kbh[ks][3] };
                    uint32_t b0l[2] = { kbl[ks][0], kbl[ks][2] };
                    uint32_t b1l[2] = { kbl[ks][1], kbl[ks][3] };
                    mma_bf16(sS[2 * ntp],     qfh[ks], b0h);
                    mma_bf16(sS[2 * ntp],     qfh[ks], b0l);
                    mma_bf16(sS[2 * ntp],     qfl[ks], b0h);
                    mma_bf16(sS[2 * ntp + 1], qfh[ks], b1h);
                    mma_bf16(sS[2 * ntp + 1], qfh[ks], b1l);
                    mma_bf16(sS[2 * ntp + 1], qfl[ks], b1h);
                }
            }
        }

        // ---- causal mask (diagonal tile only) ----
        if (kt == qt) {
            #pragma unroll
            for (int nt = 0; nt < 8; nt++) {
                const int kn = nt * 8 + 2 * (lane & 3);
                if (kn > qrow_lo0)     sS[nt][0] = -1e30f;
                if (kn + 1 > qrow_lo0) sS[nt][1] = -1e30f;
                if (kn > qrow_lo1)     sS[nt][2] = -1e30f;
                if (kn + 1 > qrow_lo1) sS[nt][3] = -1e30f;
            }
        }

        // ---- online softmax ----
        float rmax0 = -1e30f, rmax1 = -1e30f;
        #pragma unroll
        for (int nt = 0; nt < 8; nt++) {
            rmax0 = fmaxf(rmax0, fmaxf(sS[nt][0], sS[nt][1]));
            rmax1 = fmaxf(rmax1, fmaxf(sS[nt][2], sS[nt][3]));
        }
        rmax0 = fmaxf(rmax0, __shfl_xor_sync(0xffffffff, rmax0, 1));
        rmax0 = fmaxf(rmax0, __shfl_xor_sync(0xffffffff, rmax0, 2));
        rmax1 = fmaxf(rmax1, __shfl_xor_sync(0xffffffff, rmax1, 1));
        rmax1 = fmaxf(rmax1, __shfl_xor_sync(0xffffffff, rmax1, 2));

        const float mnew0 = fmaxf(mrun0, rmax0);
        const float mnew1 = fmaxf(mrun1, rmax1);
        const float corr0 = __expf(mrun0 - mnew0);
        const float corr1 = __expf(mrun1 - mnew1);
        mrun0 = mnew0; mrun1 = mnew1;

        float rsum0 = 0.f, rsum1 = 0.f;
        #pragma unroll
        for (int nt = 0; nt < 8; nt++) {
            sS[nt][0] = __expf(sS[nt][0] - mnew0);
            sS[nt][1] = __expf(sS[nt][1] - mnew0);
            sS[nt][2] = __expf(sS[nt][2] - mnew1);
            sS[nt][3] = __expf(sS[nt][3] - mnew1);
            rsum0 += sS[nt][0] + sS[nt][1];
            rsum1 += sS[nt][2] + sS[nt][3];
        }
        rsum0 += __shfl_xor_sync(0xffffffff, rsum0, 1);
        rsum0 += __shfl_xor_sync(0xffffffff, rsum0, 2);
        rsum1 += __shfl_xor_sync(0xffffffff, rsum1, 1);
        rsum1 += __shfl_xor_sync(0xffffffff, rsum1, 2);
        lrun0 = lrun0 * corr0 + rsum0;
        lrun1 = lrun1 * corr1 + rsum1;

        #pragma unroll
        for (int dt = 0; dt < 8; dt++) {
            O[dt][0] *= corr0; O[dt][1] *= corr0;
            O[dt][2] *= corr1; O[dt][3] *= corr1;
        }

        // ---- O += P @ V (split P, split V) ----
        {
            const int vrow = lane & 15;
            const int vcol = (lane >> 4) * 8;
            #pragma unroll
            for (int j = 0; j < 4; j++) {     // k16 chunk = S tiles 2j, 2j+1
                // P fragments from S (C->A register identity)
                uint32_t ph[4], pl[4];
                #pragma unroll
                for (int half = 0; half < 2; half++) {
                    const float p0 = sS[2 * j + half][0], p1 = sS[2 * j + half][1];
                    const float p2 = sS[2 * j + half][2], p3 = sS[2 * j + half][3];
                    __nv_bfloat16 h0 = __float2bfloat16(p0), h1 = __float2bfloat16(p1);
                    __nv_bfloat16 h2 = __float2bfloat16(p2), h3 = __float2bfloat16(p3);
                    ph[2 * half + 0] = pack_bf16(h0, h1);
                    ph[2 * half + 1] = pack_bf16(h2, h3);
                    pl[2 * half + 0] = pack_bf16(__float2bfloat16(p0 - __bfloat162float(h0)),
                                                 __float2bfloat16(p1 - __bfloat162float(h1)));
                    pl[2 * half + 1] = pack_bf16(__float2bfloat16(p2 - __bfloat162float(h2)),
                                                 __float2bfloat16(p3 - __bfloat162float(h3)));
                }
                // V fragments via ldmatrix.trans
                uint32_t vh[4][4], vl[4][4];
                #pragma unroll
                for (int db = 0; db < 4; db++) {
                    const uint32_t off = (uint32_t)((j * 16 + vrow) * (AST * 2)
                                                    + (db * 16 + vcol) * 2);
                    ldmatrix_x4_trans(vh[db][0], vh[db][1], vh[db][2], vh[db][3], sVh + off);
                    ldmatrix_x4_trans(vl[db][0], vl[db][1], vl[db][2], vl[db][3], sVl + off);
                }
                #pragma unroll
                for (int dt = 0; dt < 8; dt++) {
                    const int db = dt >> 1, pr = dt & 1;
                    uint32_t bh[2] = { vh[db][2 * pr], vh[db][2 * pr + 1] };
                    uint32_t bl[2] = { vl[db][2 * pr], vl[db][2 * pr + 1] };
                    mma_bf16(O[dt], ph, bh);
                    mma_bf16(O[dt], ph, bl);
                    mma_bf16(O[dt], pl, bh);
                }
            }
        }
    }

    // ---- normalize + write yh/yl ----
    const float inv0 = 1.f / lrun0;
    const float inv1 = 1.f / lrun1;
    const int m0g = b * TT + qt * 64 + warp * 16 + (lane >> 2);
    const int colb = h * HD + 2 * (lane & 3);
    #pragma unroll
    for (int dt = 0; dt < 8; dt++) {
        const int col = colb + dt * 8;
        {
            float v0 = O[dt][0] * inv0, v1 = O[dt][1] * inv0;
            __nv_bfloat16 h0 = __float2bfloat16(v0), h1 = __float2bfloat16(v1);
            *(uint32_t*)(g_yh + (size_t)m0g * CC + col) = pack_bf16(h0, h1);
            *(uint32_t*)(g_yl + (size_t)m0g * CC + col) =
                pack_bf16(__float2bfloat16(v0 - __bfloat162float(h0)),
                          __float2bfloat16(v1 - __bfloat162float(h1)));
        }
        {
            float v0 = O[dt][2] * inv1, v1 = O[dt][3] * inv1;
            __nv_bfloat16 h0 = __float2bfloat16(v0), h1 = __float2bfloat16(v1);
            *(uint32_t*)(g_yh + (size_t)(m0g + 8) * CC + col) = pack_bf16(h0, h1);
            *(uint32_t*)(g_yl + (size_t)(m0g + 8) * CC + col) =
                pack_bf16(__float2bfloat16(v0 - __bfloat162float(h0)),
                          __float2bfloat16(v1 - __bfloat162float(h1)));
        }
    }
}

// ---------------- launch -----------------------------------------------------
extern "C" void kernel_launch(void* const* d_in, const int* in_sizes, int n_in,
                              void* d_out, int out_size)
{
    (void)in_sizes; (void)n_in; (void)out_size;
    const float* x  = (const float*)d_in[0];
    const float* Wa = (const float*)d_in[1];
    const float* ba = (const float*)d_in[2];
    const float* Wp = (const float*)d_in[3];
    const float* bp = (const float*)d_in[4];
    float* out = (float*)d_out;

    cudaFuncSetAttribute(mma_gemm_kernel<0>, cudaFuncAttributeMaxDynamicSharedMemorySize, GSMEM_TOTAL);
    cudaFuncSetAttribute(mma_gemm_kernel<1>, cudaFuncAttributeMaxDynamicSharedMemorySize, GSMEM_TOTAL);
    cudaFuncSetAttribute(attn_mma_kernel, cudaFuncAttributeMaxDynamicSharedMemorySize, ASMEM);

    __nv_bfloat16 *xh, *xl, *yh, *yl, *wah, *wal, *wph, *wpl;
    cudaGetSymbolAddress((void**)&xh,  g_xh);  cudaGetSymbolAddress((void**)&xl,  g_xl);
    cudaGetSymbolAddress((void**)&yh,  g_yh);  cudaGetSymbolAddress((void**)&yl,  g_yl);
    cudaGetSymbolAddress((void**)&wah, g_wah); cudaGetSymbolAddress((void**)&wal, g_wal);
    cudaGetSymbolAddress((void**)&wph, g_wph); cudaGetSymbolAddress((void**)&wpl, g_wpl);

    // 1) split x -> bf16 hi/lo
    {
        int n4 = MM * KK / 4;
        split_kernel<<<(n4 + 255) / 256, 256>>>(x, xh, xl, n4);
    }
    // 2) transpose+split weights
    {
        dim3 blk(32, 8);
        transpose_split_kernel<<<dim3(NQKV / 32, KK / 32), blk>>>(Wa, wah, wal, KK, NQKV);
        transpose_split_kernel<<<dim3(NPROJ / 32, KK / 32), blk>>>(Wp, wph, wpl, KK, NPROJ);
    }
    // 3) QKV GEMM -> split Q/K/V in [B,H,T,64] (Q pre-scaled by 0.125)
    mma_gemm_kernel<1><<<dim3(NQKV / 128, MM / 128), 256, GSMEM_TOTAL>>>(
        xh, xl, wah, wal, ba, nullptr, NQKV, KK);
    // 4) tensor-core causal flash attention -> yh/yl
    attn_mma_kernel<<<dim3(TT / 64, NH, BB), 128, ASMEM>>>();
    // 5) proj GEMM -> out (fp32 + bias)
    mma_gemm_kernel<0><<<dim3(NPROJ / 128, MM / 128), 256, GSMEM_TOTAL>>>(
        yh, yl, wph, wpl, bp, out, NPROJ, KK);
}

// round 8
// speedup vs baseline: 5.7509x; 2.5142x over previous
#include <cuda_runtime.h>
#include <cuda_fp16.h>
#include <cstdint>
#include <cstddef>

// Problem constants
#define BB 4
#define TT 2048
#define CC 1024
#define NH 16
#define HD 64
#define MM (BB * TT)          // 8192 rows
#define KK CC                 // 1024 inner dim (both GEMMs)
#define NQKV (3 * CC)         // 3072
#define NPROJ CC              // 1024

// ---------------- scratch (device globals; no allocations allowed) ----------
__device__ __half g_q [(size_t)MM * CC];    // [B,H,T,64], pre-scaled by 0.125
__device__ __half g_k [(size_t)MM * CC];    // [B,H,T,64]
__device__ __half g_v [(size_t)MM * CC];    // [B,H,T,64]
__device__ __half g_ya[(size_t)MM * CC];    // attention out [M][C]
__device__ __half g_xc[(size_t)MM * KK];    // x fp16 [M][K]
__device__ __half g_wat[(size_t)NQKV * KK]; // W_attn^T fp16 [N][K]
__device__ __half g_wpt[(size_t)NPROJ * KK];// W_proj^T fp16 [N][K]

// ---------------- PTX helpers (sm_80-portable only) --------------------------
__device__ __forceinline__ uint32_t smem_to_u32(const void* p) {
    uint32_t a;
    asm("{ .reg .u64 t; cvta.to.shared.u64 t, %1; cvt.u32.u64 %0, t; }" : "=r"(a) : "l"(p));
    return a;
}
__device__ __forceinline__ void cpasync16(uint32_t sm, const void* g) {
    asm volatile("cp.async.ca.shared.global [%0], [%1], 16;" :: "r"(sm), "l"(g));
}
#define CP_COMMIT() asm volatile("cp.async.commit_group;" ::: "memory")
#define CP_WAIT0()  asm volatile("cp.async.wait_group 0;" ::: "memory")

__device__ __forceinline__ void ldmatrix_x4(uint32_t& r0, uint32_t& r1, uint32_t& r2,
                                            uint32_t& r3, uint32_t addr) {
    asm volatile("ldmatrix.sync.aligned.m8n8.x4.shared.b16 {%0,%1,%2,%3}, [%4];"
                 : "=r"(r0), "=r"(r1), "=r"(r2), "=r"(r3) : "r"(addr));
}
__device__ __forceinline__ void ldmatrix_x4_trans(uint32_t& r0, uint32_t& r1, uint32_t& r2,
                                                  uint32_t& r3, uint32_t addr) {
    asm volatile("ldmatrix.sync.aligned.m8n8.x4.trans.shared.b16 {%0,%1,%2,%3}, [%4];"
                 : "=r"(r0), "=r"(r1), "=r"(r2), "=r"(r3) : "r"(addr));
}
__device__ __forceinline__ void mma_f16(float* c, const uint32_t* a, const uint32_t* b) {
    asm volatile("mma.sync.aligned.m16n8k16.row.col.f32.f16.f16.f32 "
                 "{%0,%1,%2,%3}, {%4,%5,%6,%7}, {%8,%9}, {%0,%1,%2,%3};"
                 : "+f"(c[0]), "+f"(c[1]), "+f"(c[2]), "+f"(c[3])
                 : "r"(a[0]), "r"(a[1]), "r"(a[2]), "r"(a[3]), "r"(b[0]), "r"(b[1]));
}
__device__ __forceinline__ uint32_t pack_h(__half a, __half b) {
    __half2 t; t.x = a; t.y = b;
    return *(uint32_t*)&t;
}

// ---------------- prep kernels ----------------------------------------------
// fp32 -> fp16, 8 elems/thread
__global__ __launch_bounds__(256) void convert_kernel(
    const float* __restrict__ src, __half* __restrict__ dst, int n8)
{
    int i = blockIdx.x * blockDim.x + threadIdx.x;
    if (i >= n8) return;
    float4 v0 = ((const float4*)src)[i * 2];
    float4 v1 = ((const float4*)src)[i * 2 + 1];
    uint4 o;
    o.x = pack_h(__float2half(v0.x), __float2half(v0.y));
    o.y = pack_h(__float2half(v0.z), __float2half(v0.w));
    o.z = pack_h(__float2half(v1.x), __float2half(v1.y));
    o.w = pack_h(__float2half(v1.z), __float2half(v1.w));
    ((uint4*)dst)[i] = o;
}

// transpose W [K,N] -> T [N,K] fp16
__global__ __launch_bounds__(256) void transpose_convert_kernel(
    const float* __restrict__ W, __half* __restrict__ T, int K, int N)
{
    __shared__ float tile[32][33];
    const int tx = threadIdx.x, ty = threadIdx.y;    // block (32,8)
    const int n0 = blockIdx.x * 32, k0 = blockIdx.y * 32;
    #pragma unroll
    for (int i = 0; i < 32; i += 8)
        tile[ty + i][tx] = W[(size_t)(k0 + ty + i) * N + n0 + tx];
    __syncthreads();
    #pragma unroll
    for (int i = 0; i < 32; i += 8)
        T[(size_t)(n0 + ty + i) * K + k0 + tx] = __float2half(tile[tx][ty + i]);
}

// ---------------- fp16 mma.sync GEMM -----------------------------------------
// D[m,n] = sum_k A[m,k]*B[n,k] (+bias); CTA tile 128x128, BK=64, 8 warps.
// SMEM: 2 tiles (A,B) of [128][72] fp16 (144B stride), double buffered.
// MODE 0: fp32 out + bias (proj)    MODE 1: QKV epilogue -> fp16 [B,H,T,64]
#define GST      72
#define GTILE_B  (128 * GST * 2)           // 18432 bytes
#define GSTAGE_B (2 * GTILE_B)             // 36864
#define GSMEM_TOTAL (2 * GSTAGE_B)         // 73728

template <int MODE>
__global__ __launch_bounds__(256, 2) void mma_gemm_kernel(
    const __half* __restrict__ A, const __half* __restrict__ B,
    const float* __restrict__ bias, float* __restrict__ C, int N, int K)
{
    extern __shared__ char smem[];
    const uint32_t sbase = smem_to_u32(smem);
    const int tid = threadIdx.x;
    const int wid = tid >> 5, lane = tid & 31;
    const int m0 = blockIdx.y * 128;
    const int n0 = blockIdx.x * 128;
    const int warp_m = wid >> 2;           // 0..1 -> 64 rows
    const int warp_n = wid & 3;            // 0..3 -> 32 cols

    const __half* gA = A + (size_t)m0 * K;
    const __half* gB = B + (size_t)n0 * K;

    // g2s: per tile 128 rows x 8 chunks(16B); thread does 4 chunks per tile
    auto issue_stage = [&](int stage, int kof) {
        uint32_t sb = sbase + stage * GSTAGE_B;
        #pragma unroll
        for (int t = 0; t < 2; t++) {
            const __half* g = t ? gB : gA;
            uint32_t st = sb + t * GTILE_B;
            #pragma unroll
            for (int i = 0; i < 4; i++) {
                int c = tid + i * 256;
                int row = c >> 3, ch = c & 7;
                cpasync16(st + (uint32_t)(row * (GST * 2) + ch * 16),
                          (const char*)g + (size_t)row * K * 2 + kof * 2 + ch * 16);
            }
        }
    };

    float acc[4][4][4];
    #pragma unroll
    for (int i = 0; i < 4; i++)
        #pragma unroll
        for (int j = 0; j < 4; j++)
            #pragma unroll
            for (int r = 0; r < 4; r++) acc[i][j][r] = 0.f;

    const int NC = K >> 6;                 // 16 chunks of BK=64
    issue_stage(0, 0);
    CP_COMMIT();

    const int a_row = lane & 15;
    const int a_col = (lane >> 4) * 8;
    const int b_row = ((lane >> 3) & 1) * 8 + (lane & 7);
    const int b_col = (lane >> 4) * 8;

    for (int kc = 0; kc < NC; kc++) {
        CP_WAIT0();
        __syncthreads();
        const int cur = kc & 1;
        if (kc + 1 < NC) { issue_stage(cur ^ 1, (kc + 1) << 6); CP_COMMIT(); }

        const uint32_t sA = sbase + cur * GSTAGE_B;
        const uint32_t sB = sA + GTILE_B;

        #pragma unroll
        for (int ks = 0; ks < 4; ks++) {
            const int kcol = ks * 16;
            uint32_t af[4][4];
            #pragma unroll
            for (int mt = 0; mt < 4; mt++) {
                const uint32_t off = (uint32_t)((warp_m * 64 + mt * 16 + a_row) * (GST * 2)
                                                + (kcol + a_col) * 2);
                ldmatrix_x4(af[mt][0], af[mt][1], af[mt][2], af[mt][3], sA + off);
            }
            #pragma unroll
            for (int ntp = 0; ntp < 2; ntp++) {
                uint32_t kb0, kb1, kb2, kb3;
                const uint32_t off = (uint32_t)((warp_n * 32 + ntp * 16 + b_row) * (GST * 2)
                                                + (kcol + b_col) * 2);
                ldmatrix_x4(kb0, kb1, kb2, kb3, sB + off);
                uint32_t bf0[2] = { kb0, kb2 };
                uint32_t bf1[2] = { kb1, kb3 };
                #pragma unroll
                for (int mt = 0; mt < 4; mt++) {
                    mma_f16(acc[mt][2 * ntp],     af[mt], bf0);
                    mma_f16(acc[mt][2 * ntp + 1], af[mt], bf1);
                }
            }
        }
        __syncthreads();
    }

    const int er = lane >> 2, ec = (lane & 3) * 2;
    if (MODE == 0) {
        #pragma unroll
        for (int mt = 0; mt < 4; mt++) {
            const int mrow = m0 + warp_m * 64 + mt * 16 + er;
            #pragma unroll
            for (int nt = 0; nt < 4; nt++) {
                const int ncol = n0 + warp_n * 32 + nt * 8 + ec;
                float2 v0 = { acc[mt][nt][0] + bias[ncol], acc[mt][nt][1] + bias[ncol + 1] };
                float2 v1 = { acc[mt][nt][2] + bias[ncol], acc[mt][nt][3] + bias[ncol + 1] };
                *(float2*)(C + (size_t)mrow * N + ncol) = v0;
                *(float2*)(C + (size_t)(mrow + 8) * N + ncol) = v1;
            }
        }
    } else {
        // QKV epilogue: component constant per CTA (n0 multiple of 128)
        const int comp = n0 >> 10;
        __half* dst = (comp == 0) ? g_q : (comp == 1) ? g_k : g_v;
        const float sc = (comp == 0) ? 0.125f : 1.0f;
        #pragma unroll
        for (int mt = 0; mt < 4; mt++) {
            #pragma unroll
            for (int nt = 0; nt < 4; nt++) {
                const int ncol = n0 + warp_n * 32 + nt * 8 + ec;
                const int hh = (ncol & 1023) >> 6;
                const int dd = ncol & 63;
                #pragma unroll
                for (int rr = 0; rr < 2; rr++) {
                    const int mrow = m0 + warp_m * 64 + mt * 16 + er + rr * 8;
                    const int bb = mrow >> 11, t = mrow & 2047;
                    const size_t idx = (((size_t)(bb * NH + hh)) * TT + t) * HD + dd;
                    float v0 = (acc[mt][nt][rr * 2 + 0] + bias[ncol]) * sc;
                    float v1 = (acc[mt][nt][rr * 2 + 1] + bias[ncol + 1]) * sc;
                    *(uint32_t*)(dst + idx) = pack_h(__float2half(v0), __float2half(v1));
                }
            }
        }
    }
}

// ---------------- tensor-core causal flash attention (fp16) ------------------
// CTA: 64 query rows, 4 warps (16 rows each). Key tiles of 64, double-buffered.
#define AST      72                         // 144B row stride
#define ATILE_B  (64 * AST * 2)             // 9216 bytes
#define ASTAGE_B (2 * ATILE_B)              // 18432 (K,V)
#define ASMEM    (2 * ASTAGE_B)             // 36864

__global__ __launch_bounds__(128) void attn_mma_kernel()
{
    extern __shared__ char smem[];
    const uint32_t sbase = smem_to_u32(smem);
    const int tid = threadIdx.x;
    const int warp = tid >> 5, lane = tid & 31;
    const int qt = blockIdx.x, h = blockIdx.y, b = blockIdx.z;

    const size_t plane = ((size_t)(b * NH + h)) * TT * HD;
    const __half* Q = g_q + plane;
    const __half* K = g_k + plane;
    const __half* V = g_v + plane;

    // ---- load Q tile into stage0 slot 0 ----
    {
        const __half* src = Q + (size_t)qt * 64 * HD;
        #pragma unroll
        for (int i = 0; i < 4; i++) {
            int c = tid + i * 128;
            int row = c >> 3, ch = c & 7;
            cpasync16(sbase + (uint32_t)(row * (AST * 2) + ch * 16),
                      (const char*)src + (size_t)row * 128 + ch * 16);
        }
    }
    CP_COMMIT();
    CP_WAIT0();
    __syncthreads();

    // ---- Q fragments ----
    uint32_t qf[4][4];
    {
        const int a_row = lane & 15;
        const int a_col = (lane >> 4) * 8;
        #pragma unroll
        for (int ks = 0; ks < 4; ks++) {
            const uint32_t off = (uint32_t)((warp * 16 + a_row) * (AST * 2)
                                            + (ks * 16 + a_col) * 2);
            ldmatrix_x4(qf[ks][0], qf[ks][1], qf[ks][2], qf[ks][3], sbase + off);
        }
    }
    __syncthreads();

    auto issue_kv = [&](int stage, int kt) {
        const __half* src[2] = { K + (size_t)kt * 64 * HD, V + (size_t)kt * 64 * HD };
        uint32_t sb = sbase + stage * ASTAGE_B;
        #pragma unroll
        for (int t = 0; t < 2; t++)
            #pragma unroll
            for (int i = 0; i < 4; i++) {
                int c = tid + i * 128;
                int row = c >> 3, ch = c & 7;
                cpasync16(sb + t * ATILE_B + (uint32_t)(row * (AST * 2) + ch * 16),
                          (const char*)src[t] + (size_t)row * 128 + ch * 16);
            }
    };

    issue_kv(0, 0);
    CP_COMMIT();

    float O[8][4];
    #pragma unroll
    for (int i = 0; i < 8; i++)
        #pragma unroll
        for (int j = 0; j < 4; j++) O[i][j] = 0.f;
    float mrun0 = -1e30f, mrun1 = -1e30f, lrun0 = 0.f, lrun1 = 0.f;

    const int qrow_lo0 = warp * 16 + (lane >> 2);
    const int qrow_lo1 = qrow_lo0 + 8;

    for (int kt = 0; kt <= qt; kt++) {
        CP_WAIT0();
        __syncthreads();
        const int cur = kt & 1;
        if (kt < qt) { issue_kv(cur ^ 1, kt + 1); CP_COMMIT(); }

        const uint32_t sK = sbase + cur * ASTAGE_B;
        const uint32_t sV = sK + ATILE_B;

        // ---- S = Q @ K^T ----
        float sS[8][4];
        #pragma unroll
        for (int i = 0; i < 8; i++)
            #pragma unroll
            for (int j = 0; j < 4; j++) sS[i][j] = 0.f;
        {
            const int krow = ((lane >> 3) & 1) * 8 + (lane & 7);
            const int kcol = (lane >> 4) * 8;
            #pragma unroll
            for (int ntp = 0; ntp < 4; ntp++) {
                #pragma unroll
                for (int ks = 0; ks < 4; ks++) {
                    uint32_t k0, k1, k2, k3;
                    const uint32_t off = (uint32_t)((ntp * 16 + krow) * (AST * 2)
                                                    + (ks * 16 + kcol) * 2);
                    ldmatrix_x4(k0, k1, k2, k3, sK + off);
                    uint32_t b0[2] = { k0, k2 };
                    uint32_t b1[2] = { k1, k3 };
                    mma_f16(sS[2 * ntp],     qf[ks], b0);
                    mma_f16(sS[2 * ntp + 1], qf[ks], b1);
                }
            }
        }

        // ---- causal mask (diagonal tile only) ----
        if (kt == qt) {
            #pragma unroll
            for (int nt = 0; nt < 8; nt++) {
                const int kn = nt * 8 + 2 * (lane & 3);
                if (kn > qrow_lo0)     sS[nt][0] = -1e30f;
                if (kn + 1 > qrow_lo0) sS[nt][1] = -1e30f;
                if (kn > qrow_lo1)     sS[nt][2] = -1e30f;
                if (kn + 1 > qrow_lo1) sS[nt][3] = -1e30f;
            }
        }

        // ---- online softmax ----
        float rmax0 = -1e30f, rmax1 = -1e30f;
        #pragma unroll
        for (int nt = 0; nt < 8; nt++) {
            rmax0 = fmaxf(rmax0, fmaxf(sS[nt][0], sS[nt][1]));
            rmax1 = fmaxf(rmax1, fmaxf(sS[nt][2], sS[nt][3]));
        }
        rmax0 = fmaxf(rmax0, __shfl_xor_sync(0xffffffff, rmax0, 1));
        rmax0 = fmaxf(rmax0, __shfl_xor_sync(0xffffffff, rmax0, 2));
        rmax1 = fmaxf(rmax1, __shfl_xor_sync(0xffffffff, rmax1, 1));
        rmax1 = fmaxf(rmax1, __shfl_xor_sync(0xffffffff, rmax1, 2));

        const float mnew0 = fmaxf(mrun0, rmax0);
        const float mnew1 = fmaxf(mrun1, rmax1);
        const float corr0 = __expf(mrun0 - mnew0);
        const float corr1 = __expf(mrun1 - mnew1);
        mrun0 = mnew0; mrun1 = mnew1;

        float rsum0 = 0.f, rsum1 = 0.f;
        #pragma unroll
        for (int nt = 0; nt < 8; nt++) {
            sS[nt][0] = __expf(sS[nt][0] - mnew0);
            sS[nt][1] = __expf(sS[nt][1] - mnew0);
            sS[nt][2] = __expf(sS[nt][2] - mnew1);
            sS[nt][3] = __expf(sS[nt][3] - mnew1);
            rsum0 += sS[nt][0] + sS[nt][1];
            rsum1 += sS[nt][2] + sS[nt][3];
        }
        rsum0 += __shfl_xor_sync(0xffffffff, rsum0, 1);
        rsum0 += __shfl_xor_sync(0xffffffff, rsum0, 2);
        rsum1 += __shfl_xor_sync(0xffffffff, rsum1, 1);
        rsum1 += __shfl_xor_sync(0xffffffff, rsum1, 2);
        lrun0 = lrun0 * corr0 + rsum0;
        lrun1 = lrun1 * corr1 + rsum1;

        #pragma unroll
        for (int dt = 0; dt < 8; dt++) {
            O[dt][0] *= corr0; O[dt][1] *= corr0;
            O[dt][2] *= corr1; O[dt][3] *= corr1;
        }

        // ---- O += P @ V ----
        {
            const int vrow = lane & 15;
            const int vcol = (lane >> 4) * 8;
            #pragma unroll
            for (int j = 0; j < 4; j++) {
                uint32_t ph[4];
                #pragma unroll
                for (int half = 0; half < 2; half++) {
                    ph[2 * half + 0] = pack_h(__float2half(sS[2 * j + half][0]),
                                              __float2half(sS[2 * j + half][1]));
                    ph[2 * half + 1] = pack_h(__float2half(sS[2 * j + half][2]),
                                              __float2half(sS[2 * j + half][3]));
                }
                uint32_t vf[4][4];
                #pragma unroll
                for (int db = 0; db < 4; db++) {
                    const uint32_t off = (uint32_t)((j * 16 + vrow) * (AST * 2)
                                                    + (db * 16 + vcol) * 2);
                    ldmatrix_x4_trans(vf[db][0], vf[db][1], vf[db][2], vf[db][3], sV + off);
                }
                #pragma unroll
                for (int dt = 0; dt < 8; dt++) {
                    const int db = dt >> 1, pr = dt & 1;
                    uint32_t bf[2] = { vf[db][2 * pr], vf[db][2 * pr + 1] };
                    mma_f16(O[dt], ph, bf);
                }
            }
        }
    }

    // ---- normalize + write y fp16 ----
    const float inv0 = 1.f / lrun0;
    const float inv1 = 1.f / lrun1;
    const int m0g = b * TT + qt * 64 + warp * 16 + (lane >> 2);
    const int colb = h * HD + 2 * (lane & 3);
    #pragma unroll
    for (int dt = 0; dt < 8; dt++) {
        const int col = colb + dt * 8;
        *(uint32_t*)(g_ya + (size_t)m0g * CC + col) =
            pack_h(__float2half(O[dt][0] * inv0), __float2half(O[dt][1] * inv0));
        *(uint32_t*)(g_ya + (size_t)(m0g + 8) * CC + col) =
            pack_h(__float2half(O[dt][2] * inv1), __float2half(O[dt][3] * inv1));
    }
}

// ---------------- launch -----------------------------------------------------
extern "C" void kernel_launch(void* const* d_in, const int* in_sizes, int n_in,
                              void* d_out, int out_size)
{
    (void)in_sizes; (void)n_in; (void)out_size;
    const float* x  = (const float*)d_in[0];
    const float* Wa = (const float*)d_in[1];
    const float* ba = (const float*)d_in[2];
    const float* Wp = (const float*)d_in[3];
    const float* bp = (const float*)d_in[4];
    float* out = (float*)d_out;

    cudaFuncSetAttribute(mma_gemm_kernel<0>, cudaFuncAttributeMaxDynamicSharedMemorySize, GSMEM_TOTAL);
    cudaFuncSetAttribute(mma_gemm_kernel<1>, cudaFuncAttributeMaxDynamicSharedMemorySize, GSMEM_TOTAL);
    cudaFuncSetAttribute(attn_mma_kernel, cudaFuncAttributeMaxDynamicSharedMemorySize, ASMEM);

    __half *xc, *wat, *wpt, *ya;
    cudaGetSymbolAddress((void**)&xc,  g_xc);
    cudaGetSymbolAddress((void**)&wat, g_wat);
    cudaGetSymbolAddress((void**)&wpt, g_wpt);
    cudaGetSymbolAddress((void**)&ya,  g_ya);

    // 1) convert x -> fp16
    {
        int n8 = MM * KK / 8;
        convert_kernel<<<(n8 + 255) / 256, 256>>>(x, xc, n8);
    }
    // 2) transpose+convert weights
    {
        dim3 blk(32, 8);
        transpose_convert_kernel<<<dim3(NQKV / 32, KK / 32), blk>>>(Wa, wat, KK, NQKV);
        transpose_convert_kernel<<<dim3(NPROJ / 32, KK / 32), blk>>>(Wp, wpt, KK, NPROJ);
    }
    // 3) QKV GEMM -> fp16 Q/K/V in [B,H,T,64] (Q pre-scaled by 0.125)
    mma_gemm_kernel<1><<<dim3(NQKV / 128, MM / 128), 256, GSMEM_TOTAL>>>(
        xc, wat, ba, nullptr, NQKV, KK);
    // 4) tensor-core causal flash attention -> y fp16
    attn_mma_kernel<<<dim3(TT / 64, NH, BB), 128, ASMEM>>>();
    // 5) proj GEMM -> out (fp32 + bias)
    mma_gemm_kernel<0><<<dim3(NPROJ / 128, MM / 128), 256, GSMEM_TOTAL>>>(
        ya, wpt, bp, out, NPROJ, KK);
}